// round 15
// baseline (speedup 1.0000x reference)
#include <cuda_runtime.h>
#include <math.h>

// Problem shape (fixed by the dataset)
#define T_LEN    4096
#define D_DIM    1024
#define MAX_B    8
#define C_CHUNKS 32
#define L_CHUNK  (T_LEN / C_CHUNKS)   // 128
#define LOG2_L   7                     // L_CHUNK = 2^7
#define NBLK     592                   // 148 SMs x 4 CTAs: all co-resident

// Scratch (device globals — no allocation in kernel_launch, per harness rules)
__device__ float g_Slocal[MAX_B * C_CHUNKS * D_DIM];        // 1 MB
// Monotonic grid-barrier counter: never reset, so graph replays stay
// deterministic (each launch consumes exactly gridSize increments).
__device__ unsigned long long g_arrive = 0ULL;

// ---------------------------------------------------------------------------
// Single kernel, two modes selected by a GRID-UNIFORM predicate:
//
//   need_fix = OR over all channels d of (c_d * tanh(logit_a_d) != 0)
//
// Every block spans the full D=1024 channels (256 thr x 4), so every block
// computes the same predicate.
//
//   !need_fix: c*s_t == c*b*u_t for every t (the a-term is annihilated), so
//              the output is POINTWISE: y = fmaf(c, b*u, d*u) — exactly the
//              reference op order when c*a == 0. Each block streams one
//              CONTIGUOUS slab of rows (max DRAM page locality), pointer-
//              increment loop (no per-iter index math), unroll 4 for MLP.
//   need_fix:  generic chunked-scan path (R11/R13-proven): blocks < 256 do
//              the local scan + Slocal, ALL blocks arrive at the grid-wide
//              monotonic-epoch barrier (592 co-resident, deadlock-free),
//              blocks < 256 then Horner-combine carries and RMW-fix y.
// ---------------------------------------------------------------------------
__global__ __launch_bounds__(256, 4)
void ssm_onepass(const float* __restrict__ x,
                 const float* __restrict__ logit_a,
                 const float* __restrict__ bvec,
                 const float* __restrict__ cvec,
                 const float* __restrict__ dvec,
                 float* __restrict__ y,
                 int nrows,       // B * T_LEN
                 int nwork)       // C_CHUNKS * B  (generic-path blocks)
{
    const int dc = threadIdx.x * 4;     // channel base (256 thr x 4 = D)

    const float4 la = *reinterpret_cast<const float4*>(logit_a + dc);
    const float4 bb = *reinterpret_cast<const float4*>(bvec + dc);
    const float4 cc = *reinterpret_cast<const float4*>(cvec + dc);
    const float4 dd = *reinterpret_cast<const float4*>(dvec + dc);
    const float ax = tanhf(la.x), ay = tanhf(la.y),
                az = tanhf(la.z), aw = tanhf(la.w);

    // Grid-uniform predicate: does any channel need a cross-chunk state?
    const int mine_ca = (cc.x * ax != 0.f) | (cc.y * ay != 0.f) |
                        (cc.z * az != 0.f) | (cc.w * aw != 0.f);
    const int need_fix = __syncthreads_or(mine_ca);

    const int row4 = D_DIM / 4;

    if (!need_fix) {
        // ---------- Lean path: pointwise y = c*(b*u) + d*u ----------
        // Balanced contiguous partition: first `extra` blocks get qr+1 rows.
        const int p     = blockIdx.x;
        const int qr    = nrows / NBLK;              // 55
        const int extra = nrows - qr * NBLK;         // 208
        const int start = p * qr + (p < extra ? p : extra);
        const int count = qr + (p < extra ? 1 : 0);

        const float4* xq = reinterpret_cast<const float4*>(x)
                           + (size_t)start * row4 + threadIdx.x;
        float4*       yq = reinterpret_cast<float4*>(y)
                           + (size_t)start * row4 + threadIdx.x;

        #pragma unroll 4
        for (int r = 0; r < count; ++r) {
            float4 u = *xq;
            float4 o;
            // exact reference order: state = b*u ; y = fmaf(c, state, d*u)
            o.x = fmaf(cc.x, bb.x * u.x, dd.x * u.x);
            o.y = fmaf(cc.y, bb.y * u.y, dd.y * u.y);
            o.z = fmaf(cc.z, bb.z * u.z, dd.z * u.z);
            o.w = fmaf(cc.w, bb.w * u.w, dd.w * u.w);
            *yq = o;
            xq += row4;
            yq += row4;
        }
        return;
    }

    // ---------------- Generic path: phase 1 (blocks < nwork) ----------------
    const int w = blockIdx.x;
    const int j = w % C_CHUNKS;          // chunk
    const int b = w / C_CHUNKS;          // batch

    float4* yp = 0;
    const size_t base = ((size_t)b * T_LEN + (size_t)j * L_CHUNK) * D_DIM + dc;

    if (w < nwork) {
        const float4* xp = reinterpret_cast<const float4*>(x + base);
        yp = reinterpret_cast<float4*>(y + base);

        float sx = 0.f, sy = 0.f, sz = 0.f, sw = 0.f;
        #pragma unroll 8
        for (int t = 0; t < L_CHUNK; ++t) {
            float4 u = xp[(size_t)t * row4];
            sx = fmaf(ax, sx, bb.x * u.x);
            sy = fmaf(ay, sy, bb.y * u.y);
            sz = fmaf(az, sz, bb.z * u.z);
            sw = fmaf(aw, sw, bb.w * u.w);
            float4 o;
            o.x = fmaf(cc.x, sx, dd.x * u.x);
            o.y = fmaf(cc.y, sy, dd.y * u.y);
            o.z = fmaf(cc.z, sz, dd.z * u.z);
            o.w = fmaf(cc.w, sw, dd.w * u.w);
            yp[(size_t)t * row4] = o;
        }
        *reinterpret_cast<float4*>(
            g_Slocal + ((size_t)b * C_CHUNKS + j) * D_DIM + dc)
            = make_float4(sx, sy, sz, sw);
    }

    // Grid-wide barrier (monotonic epoch; ALL blocks arrive, 592 co-resident)
    __threadfence();
    __syncthreads();
    if (threadIdx.x == 0) {
        unsigned long long old = atomicAdd(&g_arrive, 1ULL);
        unsigned long long target = (old / (unsigned long long)NBLK + 1ULL)
                                    * (unsigned long long)NBLK;
        while (*((volatile unsigned long long*)&g_arrive) < target) { }
    }
    __syncthreads();
    __threadfence();

    if (w >= nwork) return;

    // ---------------- Generic path: phase 2 (carry + fix-up) ----------------
    float mx = ax, my = ay, mz = az, mw = aw;
    #pragma unroll
    for (int i = 0; i < LOG2_L; ++i) { mx *= mx; my *= my; mz *= mz; mw *= mw; }

    float cx = 0.f, cy = 0.f, cz = 0.f, cw = 0.f;
    const float4* slb = reinterpret_cast<const float4*>(
        g_Slocal + (size_t)b * C_CHUNKS * D_DIM + dc);
    const int q4 = D_DIM / 4;
    #pragma unroll
    for (int i = 0; i < C_CHUNKS - 1; ++i) {
        if (i < j) {
            const float4 sl = __ldcg(slb + (size_t)i * q4);
            cx = fmaf(mx, cx, sl.x);
            cy = fmaf(my, cy, sl.y);
            cz = fmaf(mz, cz, sl.z);
            cw = fmaf(mw, cw, sl.w);
        }
    }

    float gx = cc.x * ax * cx, gy = cc.y * ay * cy,
          gz = cc.z * az * cz, gw = cc.w * aw * cw;

    const int mine = (gx != 0.f) | (gy != 0.f) | (gz != 0.f) | (gw != 0.f);
    if (!__syncthreads_or(mine)) return;   // this chunk's corrections all zero

    #pragma unroll 8
    for (int t = 0; t < L_CHUNK; ++t) {
        float4 o = yp[(size_t)t * row4];
        o.x += gx; o.y += gy; o.z += gz; o.w += gw;   // c * a^(t+1) * Sin
        yp[(size_t)t * row4] = o;
        gx *= ax; gy *= ay; gz *= az; gw *= aw;
    }
}

// ---------------------------------------------------------------------------
// Launch: inputs in metadata order: x, logit_a, b, c, d. Output fp32 (B,T,D).
// ---------------------------------------------------------------------------
extern "C" void kernel_launch(void* const* d_in, const int* in_sizes, int n_in,
                              void* d_out, int out_size)
{
    const float* x  = (const float*)d_in[0];
    const float* la = (const float*)d_in[1];
    const float* bv = (const float*)d_in[2];
    const float* cv = (const float*)d_in[3];
    const float* dv = (const float*)d_in[4];
    float* y = (float*)d_out;

    const int B = in_sizes[0] / (T_LEN * D_DIM);   // = 8

    ssm_onepass<<<NBLK, 256>>>(x, la, bv, cv, dv, y,
                               B * T_LEN, C_CHUNKS * B);
}

// round 16
// speedup vs baseline: 1.0183x; 1.0183x over previous
#include <cuda_runtime.h>
#include <math.h>

// Problem shape (fixed by the dataset)
#define T_LEN    4096
#define D_DIM    1024
#define MAX_B    8
#define C_CHUNKS 32
#define L_CHUNK  (T_LEN / C_CHUNKS)   // 128
#define LOG2_L   7                     // L_CHUNK = 2^7
#define NBLK     592                   // 148 SMs x 4 CTAs: all co-resident

// Scratch (device globals — no allocation in kernel_launch, per harness rules)
__device__ float g_Slocal[MAX_B * C_CHUNKS * D_DIM];        // 1 MB
// Monotonic grid-barrier counter: never reset, so graph replays stay
// deterministic (each launch consumes exactly gridSize increments).
__device__ unsigned long long g_arrive = 0ULL;

// ---------------------------------------------------------------------------
// Single kernel, two modes selected by a GRID-UNIFORM predicate:
//
//   need_fix = OR over all channels d of (c_d * tanh(logit_a_d) != 0)
//
// Every block spans the full D=1024 channels (256 thr x 4), so every block
// computes the same predicate.
//
//   !need_fix: c*s_t == c*b*u_t for every t (the a-term is annihilated), so
//              the output is POINTWISE: y = fmaf(c, b*u, d*u) — exactly the
//              reference op order when c*a == 0. Interleaved row grid-stride
//              (R14-proven best: 38.3us @ 5.63 TB/s), unroll 8 for deep MLP.
//   need_fix:  generic chunked-scan path (R11/R13-proven): blocks < 256 do
//              the local scan + Slocal, ALL blocks arrive at the grid-wide
//              monotonic-epoch barrier (592 co-resident, deadlock-free),
//              blocks < 256 then Horner-combine carries and RMW-fix y.
// ---------------------------------------------------------------------------
__global__ __launch_bounds__(256, 4)
void ssm_onepass(const float* __restrict__ x,
                 const float* __restrict__ logit_a,
                 const float* __restrict__ bvec,
                 const float* __restrict__ cvec,
                 const float* __restrict__ dvec,
                 float* __restrict__ y,
                 int nrows,       // B * T_LEN
                 int nwork)       // C_CHUNKS * B  (generic-path blocks)
{
    const int dc = threadIdx.x * 4;     // channel base (256 thr x 4 = D)

    const float4 la = *reinterpret_cast<const float4*>(logit_a + dc);
    const float4 bb = *reinterpret_cast<const float4*>(bvec + dc);
    const float4 cc = *reinterpret_cast<const float4*>(cvec + dc);
    const float4 dd = *reinterpret_cast<const float4*>(dvec + dc);
    const float ax = tanhf(la.x), ay = tanhf(la.y),
                az = tanhf(la.z), aw = tanhf(la.w);

    // Grid-uniform predicate: does any channel need a cross-chunk state?
    const int mine_ca = (cc.x * ax != 0.f) | (cc.y * ay != 0.f) |
                        (cc.z * az != 0.f) | (cc.w * aw != 0.f);
    const int need_fix = __syncthreads_or(mine_ca);

    const int row4 = D_DIM / 4;

    if (!need_fix) {
        // ---------- Lean path: pointwise y = c*(b*u) + d*u ----------
        // Interleaved grid-stride over rows (R14-proven DRAM pattern).
        const float4* xq = reinterpret_cast<const float4*>(x) + threadIdx.x;
        float4*       yq = reinterpret_cast<float4*>(y) + threadIdx.x;
        #pragma unroll 8
        for (int r = blockIdx.x; r < nrows; r += NBLK) {
            const size_t off = (size_t)r * row4;
            float4 u = xq[off];
            float4 o;
            // exact reference order: state = b*u ; y = fmaf(c, state, d*u)
            o.x = fmaf(cc.x, bb.x * u.x, dd.x * u.x);
            o.y = fmaf(cc.y, bb.y * u.y, dd.y * u.y);
            o.z = fmaf(cc.z, bb.z * u.z, dd.z * u.z);
            o.w = fmaf(cc.w, bb.w * u.w, dd.w * u.w);
            yq[off] = o;
        }
        return;
    }

    // ---------------- Generic path: phase 1 (blocks < nwork) ----------------
    const int w = blockIdx.x;
    const int j = w % C_CHUNKS;          // chunk
    const int b = w / C_CHUNKS;          // batch

    float4* yp = 0;
    const size_t base = ((size_t)b * T_LEN + (size_t)j * L_CHUNK) * D_DIM + dc;

    if (w < nwork) {
        const float4* xp = reinterpret_cast<const float4*>(x + base);
        yp = reinterpret_cast<float4*>(y + base);

        float sx = 0.f, sy = 0.f, sz = 0.f, sw = 0.f;
        #pragma unroll 8
        for (int t = 0; t < L_CHUNK; ++t) {
            float4 u = xp[(size_t)t * row4];
            sx = fmaf(ax, sx, bb.x * u.x);
            sy = fmaf(ay, sy, bb.y * u.y);
            sz = fmaf(az, sz, bb.z * u.z);
            sw = fmaf(aw, sw, bb.w * u.w);
            float4 o;
            o.x = fmaf(cc.x, sx, dd.x * u.x);
            o.y = fmaf(cc.y, sy, dd.y * u.y);
            o.z = fmaf(cc.z, sz, dd.z * u.z);
            o.w = fmaf(cc.w, sw, dd.w * u.w);
            yp[(size_t)t * row4] = o;
        }
        *reinterpret_cast<float4*>(
            g_Slocal + ((size_t)b * C_CHUNKS + j) * D_DIM + dc)
            = make_float4(sx, sy, sz, sw);
    }

    // Grid-wide barrier (monotonic epoch; ALL blocks arrive, 592 co-resident)
    __threadfence();
    __syncthreads();
    if (threadIdx.x == 0) {
        unsigned long long old = atomicAdd(&g_arrive, 1ULL);
        unsigned long long target = (old / (unsigned long long)NBLK + 1ULL)
                                    * (unsigned long long)NBLK;
        while (*((volatile unsigned long long*)&g_arrive) < target) { }
    }
    __syncthreads();
    __threadfence();

    if (w >= nwork) return;

    // ---------------- Generic path: phase 2 (carry + fix-up) ----------------
    float mx = ax, my = ay, mz = az, mw = aw;
    #pragma unroll
    for (int i = 0; i < LOG2_L; ++i) { mx *= mx; my *= my; mz *= mz; mw *= mw; }

    float cx = 0.f, cy = 0.f, cz = 0.f, cw = 0.f;
    const float4* slb = reinterpret_cast<const float4*>(
        g_Slocal + (size_t)b * C_CHUNKS * D_DIM + dc);
    const int q4 = D_DIM / 4;
    #pragma unroll
    for (int i = 0; i < C_CHUNKS - 1; ++i) {
        if (i < j) {
            const float4 sl = __ldcg(slb + (size_t)i * q4);
            cx = fmaf(mx, cx, sl.x);
            cy = fmaf(my, cy, sl.y);
            cz = fmaf(mz, cz, sl.z);
            cw = fmaf(mw, cw, sl.w);
        }
    }

    float gx = cc.x * ax * cx, gy = cc.y * ay * cy,
          gz = cc.z * az * cz, gw = cc.w * aw * cw;

    const int mine = (gx != 0.f) | (gy != 0.f) | (gz != 0.f) | (gw != 0.f);
    if (!__syncthreads_or(mine)) return;   // this chunk's corrections all zero

    #pragma unroll 8
    for (int t = 0; t < L_CHUNK; ++t) {
        float4 o = yp[(size_t)t * row4];
        o.x += gx; o.y += gy; o.z += gz; o.w += gw;   // c * a^(t+1) * Sin
        yp[(size_t)t * row4] = o;
        gx *= ax; gy *= ay; gz *= az; gw *= aw;
    }
}

// ---------------------------------------------------------------------------
// Launch: inputs in metadata order: x, logit_a, b, c, d. Output fp32 (B,T,D).
// ---------------------------------------------------------------------------
extern "C" void kernel_launch(void* const* d_in, const int* in_sizes, int n_in,
                              void* d_out, int out_size)
{
    const float* x  = (const float*)d_in[0];
    const float* la = (const float*)d_in[1];
    const float* bv = (const float*)d_in[2];
    const float* cv = (const float*)d_in[3];
    const float* dv = (const float*)d_in[4];
    float* y = (float*)d_out;

    const int B = in_sizes[0] / (T_LEN * D_DIM);   // = 8

    ssm_onepass<<<NBLK, 256>>>(x, la, bv, cv, dv, y,
                               B * T_LEN, C_CHUNKS * B);
}

// round 17
// speedup vs baseline: 1.0484x; 1.0296x over previous
#include <cuda_runtime.h>
#include <math.h>

// Problem shape (fixed by the dataset)
#define T_LEN    4096
#define D_DIM    1024
#define MAX_B    8
#define C_CHUNKS 32
#define L_CHUNK  (T_LEN / C_CHUNKS)   // 128
#define LOG2_L   7                     // L_CHUNK = 2^7

// Scratch (device globals — no allocation in kernel_launch, per harness rules)
__device__ float g_Slocal[MAX_B * C_CHUNKS * D_DIM];        // 1 MB
// Monotonic grid-barrier counter: never reset, so graph replays stay
// deterministic (each launch consumes exactly gridSize increments).
__device__ unsigned long long g_arrive = 0ULL;

// ---------------------------------------------------------------------------
// Single kernel, 256 CTAs (cheapest measured end-to-end launch shape), two
// modes selected by a GRID-UNIFORM predicate:
//
//   need_fix = OR over all channels d of (c_d * tanh(logit_a_d) != 0)
//
// Every block spans the full D=1024 channels (256 thr x 4), so every block
// computes the same predicate.
//
//   !need_fix: c*s_t == c*b*u_t for every t (the a-term is annihilated), so
//              the output is POINTWISE: y = fmaf(c, b*u, d*u) — exactly the
//              reference op order when c*a == 0. Block (j,b) streams its
//              chunk's contiguous 128-row slab with no dependency chain.
//   need_fix:  generic chunked-scan path (R11/R13-proven): local scan +
//              Slocal, grid-wide monotonic-epoch barrier (256 co-resident),
//              Horner carry combine, RMW fix-up.
// ---------------------------------------------------------------------------
__global__ __launch_bounds__(256, 4)
void ssm_onepass(const float* __restrict__ x,
                 const float* __restrict__ logit_a,
                 const float* __restrict__ bvec,
                 const float* __restrict__ cvec,
                 const float* __restrict__ dvec,
                 float* __restrict__ y,
                 int nblk)
{
    const int j  = blockIdx.x;          // chunk
    const int b  = blockIdx.y;          // batch
    const int dc = threadIdx.x * 4;     // channel base (256 thr x 4 = D)

    const float4 la = *reinterpret_cast<const float4*>(logit_a + dc);
    const float4 bb = *reinterpret_cast<const float4*>(bvec + dc);
    const float4 cc = *reinterpret_cast<const float4*>(cvec + dc);
    const float4 dd = *reinterpret_cast<const float4*>(dvec + dc);
    const float ax = tanhf(la.x), ay = tanhf(la.y),
                az = tanhf(la.z), aw = tanhf(la.w);

    // Grid-uniform predicate: does any channel need a cross-chunk state?
    const int mine_ca = (cc.x * ax != 0.f) | (cc.y * ay != 0.f) |
                        (cc.z * az != 0.f) | (cc.w * aw != 0.f);
    const int need_fix = __syncthreads_or(mine_ca);

    const int row4 = D_DIM / 4;
    const size_t base = ((size_t)b * T_LEN + (size_t)j * L_CHUNK) * D_DIM + dc;
    const float4* xp = reinterpret_cast<const float4*>(x + base);
    float4*       yp = reinterpret_cast<float4*>(y + base);

    if (!need_fix) {
        // ---------- Lean path: pointwise y = c*(b*u) + d*u ----------
        // No dependency chain: pure load -> 2 FMA -> store, unroll 8.
        #pragma unroll 8
        for (int t = 0; t < L_CHUNK; ++t) {
            float4 u = xp[(size_t)t * row4];
            float4 o;
            // exact reference order: state = b*u ; y = fmaf(c, state, d*u)
            o.x = fmaf(cc.x, bb.x * u.x, dd.x * u.x);
            o.y = fmaf(cc.y, bb.y * u.y, dd.y * u.y);
            o.z = fmaf(cc.z, bb.z * u.z, dd.z * u.z);
            o.w = fmaf(cc.w, bb.w * u.w, dd.w * u.w);
            yp[(size_t)t * row4] = o;
        }
        return;
    }

    // ---------------- Generic path: phase 1 (local scan) ----------------
    {
        float sx = 0.f, sy = 0.f, sz = 0.f, sw = 0.f;
        #pragma unroll 8
        for (int t = 0; t < L_CHUNK; ++t) {
            float4 u = xp[(size_t)t * row4];
            sx = fmaf(ax, sx, bb.x * u.x);
            sy = fmaf(ay, sy, bb.y * u.y);
            sz = fmaf(az, sz, bb.z * u.z);
            sw = fmaf(aw, sw, bb.w * u.w);
            float4 o;
            o.x = fmaf(cc.x, sx, dd.x * u.x);
            o.y = fmaf(cc.y, sy, dd.y * u.y);
            o.z = fmaf(cc.z, sz, dd.z * u.z);
            o.w = fmaf(cc.w, sw, dd.w * u.w);
            yp[(size_t)t * row4] = o;
        }
        *reinterpret_cast<float4*>(
            g_Slocal + ((size_t)b * C_CHUNKS + j) * D_DIM + dc)
            = make_float4(sx, sy, sz, sw);
    }

    // Grid-wide barrier (monotonic epoch; all 256 CTAs co-resident)
    __threadfence();
    __syncthreads();
    if (threadIdx.x == 0) {
        unsigned long long old = atomicAdd(&g_arrive, 1ULL);
        unsigned long long target = (old / (unsigned long long)nblk + 1ULL)
                                    * (unsigned long long)nblk;
        while (*((volatile unsigned long long*)&g_arrive) < target) { }
    }
    __syncthreads();
    __threadfence();

    // ---------------- Generic path: phase 2 (carry + fix-up) ----------------
    float mx = ax, my = ay, mz = az, mw = aw;
    #pragma unroll
    for (int i = 0; i < LOG2_L; ++i) { mx *= mx; my *= my; mz *= mz; mw *= mw; }

    float cx = 0.f, cy = 0.f, cz = 0.f, cw = 0.f;
    const float4* slb = reinterpret_cast<const float4*>(
        g_Slocal + (size_t)b * C_CHUNKS * D_DIM + dc);
    const int q4 = D_DIM / 4;
    #pragma unroll
    for (int i = 0; i < C_CHUNKS - 1; ++i) {
        if (i < j) {
            const float4 sl = __ldcg(slb + (size_t)i * q4);
            cx = fmaf(mx, cx, sl.x);
            cy = fmaf(my, cy, sl.y);
            cz = fmaf(mz, cz, sl.z);
            cw = fmaf(mw, cw, sl.w);
        }
    }

    float gx = cc.x * ax * cx, gy = cc.y * ay * cy,
          gz = cc.z * az * cz, gw = cc.w * aw * cw;

    const int mine = (gx != 0.f) | (gy != 0.f) | (gz != 0.f) | (gw != 0.f);
    if (!__syncthreads_or(mine)) return;   // this chunk's corrections all zero

    #pragma unroll 8
    for (int t = 0; t < L_CHUNK; ++t) {
        float4 o = yp[(size_t)t * row4];
        o.x += gx; o.y += gy; o.z += gz; o.w += gw;   // c * a^(t+1) * Sin
        yp[(size_t)t * row4] = o;
        gx *= ax; gy *= ay; gz *= az; gw *= aw;
    }
}

// ---------------------------------------------------------------------------
// Launch: inputs in metadata order: x, logit_a, b, c, d. Output fp32 (B,T,D).
// ---------------------------------------------------------------------------
extern "C" void kernel_launch(void* const* d_in, const int* in_sizes, int n_in,
                              void* d_out, int out_size)
{
    const float* x  = (const float*)d_in[0];
    const float* la = (const float*)d_in[1];
    const float* bv = (const float*)d_in[2];
    const float* cv = (const float*)d_in[3];
    const float* dv = (const float*)d_in[4];
    float* y = (float*)d_out;

    const int B = in_sizes[0] / (T_LEN * D_DIM);   // = 8

    dim3 grid(C_CHUNKS, B);                        // 256 CTAs, all co-resident
    dim3 blk(256);
    ssm_onepass<<<grid, blk>>>(x, la, bv, cv, dv, y, C_CHUNKS * B);
}